// round 8
// baseline (speedup 1.0000x reference)
#include <cuda_runtime.h>
#include <cstdint>
#include <math.h>

#define BATCH   32
#define TT      32
#define DIN     128
#define CSZ     4
#define SL      128
#define CTRLD   256
#define NHEADS  5
#define NT      512
#define MEMP    65
#define MM2C    52          // hk rows cached (of 64); 12 streamed coalesced

// ---- per-batch block (float offsets within block), block stride PB ----
#define PB       14728
#define O_MEM    0          // 8320
#define O_PX     8320       // 1920 instr partials [cta][480]; rpart[4][256] reuse
#define O_EXG    9344       // 650, overlaid on px tail (disjoint lifetime)
#define O_RWP0   10240      // 512 wt ping (float4/slot)
#define O_RWP1   10752      // 512 wt pong
#define O_WW0    11264      // 128
#define O_WW1    11392      // 128
#define O_CTRL   11520      // 384 : [x_t | rvec]
#define O_H64    11904      // 64
#define O_KV     11968      // 320
#define O_EV     12288      // 64
#define O_AV     12352      // 64
#define O_HP     12416      // 40
#define O_KRED   12456      // 10
#define O_PINV   12466      // 8
#define O_STATS  12474      // 20
#define O_SSUM   12494      // 20
#define O_HALO   12514      // 20
#define O_REDB   12534      // 80
#define O_BUF    12614      // 2112 (mm1 fold 64*33; GH partials 1024)
// shared
#define O_BCS    (2*PB)            // 29456, 64
#define O_HBS    (O_BCS + 64)      // 480
#define O_SHK    (O_HBS + 480)     // 30000, 52*480
#define SMEM_FLOATS (O_SHK + MM2C*480)   // 54960 floats = 219840 B

__device__ __forceinline__ float sigmoidf_(float v) { return 1.f / (1.f + __expf(-v)); }
__device__ __forceinline__ float softplusf_(float v) { return v > 20.f ? v : log1pf(__expf(v)); }

__device__ __forceinline__ uint32_t smem_u32(const void* p) {
    uint32_t a;
    asm("{ .reg .u64 t; cvta.to.shared.u64 t, %1; cvt.u32.u64 %0, t; }" : "=r"(a) : "l"(p));
    return a;
}
__device__ __forceinline__ uint32_t mapa_u32(uint32_t a, uint32_t rank) {
    uint32_t r;
    asm("mapa.shared::cluster.u32 %0, %1, %2;" : "=r"(r) : "r"(a), "r"(rank));
    return r;
}
__device__ __forceinline__ void st_remote(uint32_t a, float v) {
    asm volatile("st.shared::cluster.f32 [%0], %1;" :: "r"(a), "f"(v) : "memory");
}
__device__ __forceinline__ void st_remote64(uint32_t a, unsigned long long v) {
    asm volatile("st.shared::cluster.u64 [%0], %1;" :: "r"(a), "l"(v) : "memory");
}
__device__ __forceinline__ uint32_t ctarank() {
    uint32_t r; asm("mov.u32 %0, %%cluster_ctarank;" : "=r"(r)); return r;
}
#define CLUSTER_SYNC() do { \
    asm volatile("barrier.cluster.arrive.aligned;" ::: "memory"); \
    asm volatile("barrier.cluster.wait.aligned;" ::: "memory"); } while (0)

__device__ __forceinline__ unsigned long long pack2(float a, float b) {
    return (unsigned long long)__float_as_uint(a) |
           ((unsigned long long)__float_as_uint(b) << 32);
}

__global__ __launch_bounds__(NT, 1) __cluster_dims__(CSZ, 1, 1)
void ntm_kernel(const float* __restrict__ x, const float* __restrict__ Wc,
                const float* __restrict__ bc, const float* __restrict__ hk,
                const float* __restrict__ hb, float* __restrict__ out)
{
    extern __shared__ float sm[];
    float* bcs = sm + O_BCS;
    float* hbs = sm + O_HBS;
    float* SHK = sm + O_SHK;

    const int tid  = threadIdx.x;
    const int wrp  = tid >> 5;
    const int lane = tid & 31;
    const int bp   = blockIdx.x >> 2;       // batch pair id: batches 2bp, 2bp+1
    const uint32_t r = ctarank();
    const uint32_t left  = (r + 3) & 3;
    const uint32_t right = (r + 1) & 3;

    const uint32_t sbase = smem_u32(sm);
    uint32_t pb[CSZ];
#pragma unroll
    for (int c = 0; c < CSZ; ++c) pb[c] = mapa_u32(sbase, c);

    // ---- init: zero both batch blocks, load constants + caches ----
    for (int i = tid; i < 2 * PB; i += NT) sm[i] = 0.f;
    __syncthreads();
    if (tid < 5)                     sm[O_PINV + tid] = 1.f;
    else if (tid >= 8 && tid < 13)   sm[PB + O_PINV + (tid - 8)] = 1.f;
    if (tid >= 32 && tid < 160)      sm[O_CTRL + (tid - 32)] = x[(2 * bp) * TT * DIN + (tid - 32)];
    else if (tid >= 160 && tid < 288) sm[PB + O_CTRL + (tid - 160)] = x[(2 * bp + 1) * TT * DIN + (tid - 160)];
    else if (tid >= 288 && tid < 352) bcs[tid - 288] = bc[r * 64 + (tid - 288)];
    for (int i = tid; i < 478; i += NT) hbs[i] = hb[i];
    for (int kk = 0; kk < MM2C; ++kk)
        if (tid < 478) SHK[kk * 480 + tid] = hk[((int)r * 64 + kk) * 478 + tid];
    __syncthreads();
    CLUSTER_SYNC();

    for (int t = 0; t < TT; ++t) {
        const int par = t & 1;
        const int RWRD = par ? O_RWP1 : O_RWP0;
        const int RWWR = par ? O_RWP0 : O_RWP1;
        const int WWRD = par ? O_WW1 : O_WW0;
        const int WWWR = par ? O_WW0 : O_WW1;

        // ---- mm1 pass1, fused batches, coalesced Wc stream ----
        {
            const int cg = tid & 15, ks = tid >> 4;
            const float4* W4 = reinterpret_cast<const float4*>(Wc) + (int)r * 16 + cg;
            const float* c0 = sm + O_CTRL;
            const float* c1 = sm + PB + O_CTRL;
            float a0 = 0.f, a1 = 0.f, a2 = 0.f, a3 = 0.f;
            float b0 = 0.f, b1 = 0.f, b2 = 0.f, b3 = 0.f;
            const int k0 = ks * 12;
#pragma unroll
            for (int j = 0; j < 12; ++j) {
                int k = k0 + j;
                float4 w = W4[k * 64];
                float cA = c0[k], cB = c1[k];
                a0 = fmaf(cA, w.x, a0); a1 = fmaf(cA, w.y, a1);
                a2 = fmaf(cA, w.z, a2); a3 = fmaf(cA, w.w, a3);
                b0 = fmaf(cB, w.x, b0); b1 = fmaf(cB, w.y, b1);
                b2 = fmaf(cB, w.z, b2); b3 = fmaf(cB, w.w, b3);
            }
            float* bufA = sm + O_BUF;
            float* bufB = sm + PB + O_BUF;
            bufA[(cg * 4 + 0) * 33 + ks] = a0; bufA[(cg * 4 + 1) * 33 + ks] = a1;
            bufA[(cg * 4 + 2) * 33 + ks] = a2; bufA[(cg * 4 + 3) * 33 + ks] = a3;
            bufB[(cg * 4 + 0) * 33 + ks] = b0; bufB[(cg * 4 + 1) * 33 + ks] = b1;
            bufB[(cg * 4 + 2) * 33 + ks] = b2; bufB[(cg * 4 + 3) * 33 + ks] = b3;
        }
        __syncthreads();  // S0
        if (tid < 128) {
            const int half = tid >> 6, c = tid & 63;
            const float* bufX = sm + half * PB + O_BUF + c * 33;
            float acc = 0.f;
#pragma unroll
            for (int ks = 0; ks < 32; ++ks) acc += bufX[ks];
            float hv = tanhf(acc + bcs[c]);
            sm[half * PB + O_H64 + c] = hv;
            if (t == TT - 1) out[(2 * bp + half) * CTRLD + (int)r * 64 + c] = hv;
        }
        __syncthreads();  // S1

        // ---- mm2 fused: 52 cached rows + 12 streamed coalesced ----
        if (wrp < 15) {
            const int tc = (tid < 478) ? tid : 477;
            const float* h0 = sm + O_H64;
            const float* h1 = sm + PB + O_H64;
            float vA0 = 0.f, vA1 = 0.f, vA2 = 0.f, vA3 = 0.f;
            float vB0 = 0.f, vB1 = 0.f, vB2 = 0.f, vB3 = 0.f;
            const float* hkg = hk + ((int)r * 64 + MM2C) * 478 + tc;
            float sA = 0.f, sB = 0.f;
#pragma unroll
            for (int k2 = 0; k2 < 64 - MM2C; ++k2) {
                float wg = hkg[k2 * 478];
                sA = fmaf(h0[MM2C + k2], wg, sA);
                sB = fmaf(h1[MM2C + k2], wg, sB);
            }
#pragma unroll
            for (int kk = 0; kk < MM2C; kk += 4) {
                float w0 = SHK[(kk + 0) * 480 + tc];
                float w1 = SHK[(kk + 1) * 480 + tc];
                float w2 = SHK[(kk + 2) * 480 + tc];
                float w3 = SHK[(kk + 3) * 480 + tc];
                vA0 = fmaf(h0[kk + 0], w0, vA0); vB0 = fmaf(h1[kk + 0], w0, vB0);
                vA1 = fmaf(h0[kk + 1], w1, vA1); vB1 = fmaf(h1[kk + 1], w1, vB1);
                vA2 = fmaf(h0[kk + 2], w2, vA2); vB2 = fmaf(h1[kk + 2], w2, vB2);
                vA3 = fmaf(h0[kk + 3], w3, vA3); vB3 = fmaf(h1[kk + 3], w3, vB3);
            }
            float vA = ((vA0 + vA1) + (vA2 + vA3)) + sA;
            float vB = ((vB0 + vB1) + (vB2 + vB3)) + sB;
            if (tid < 478) {
                sm[O_PX + r * 480 + tid]      = vA;
                sm[PB + O_PX + r * 480 + tid] = vB;
            }
            float voA = __shfl_down_sync(0xffffffffu, vA, 1);
            float voB = __shfl_down_sync(0xffffffffu, vB, 1);
            if (!(tid & 1) && tid < 477) {
                unsigned long long pkA = pack2(vA, voA);
                unsigned long long pkB = pack2(vB, voB);
#pragma unroll
                for (int c = 0; c < CSZ; ++c)
                    if (c != (int)r) {
                        st_remote64(pb[c] + (O_PX + (int)r * 480 + tid) * 4, pkA);
                        st_remote64(pb[c] + (PB + O_PX + (int)r * 480 + tid) * 4, pkB);
                    }
            }
        }
        CLUSTER_SYNC();  // CS2

        // ---- parse x2 (sequential, full block) ----
#pragma unroll 1
        for (int bat = 0; bat < 2; ++bat) {
            const int base = bat * PB;
            const float* px = sm + base + O_PX;
            if (tid < 320) {
                int h = tid >> 6, m = tid & 63;
                int idx = (h < 4 ? h * 70 : 280) + m;
                float v = px[idx] + px[480 + idx] + px[960 + idx] + px[1440 + idx] + hbs[idx];
                sm[base + O_KV + tid] = v;
                float sq = v * v;
#pragma unroll
                for (int o = 16; o > 0; o >>= 1) sq += __shfl_xor_sync(0xffffffffu, sq, o);
                if (lane == 0) sm[base + O_KRED + wrp] = sq;
            } else if (tid < 384) {
                int idx = 350 + (tid - 320);
                sm[base + O_EV + (tid - 320)] =
                    px[idx] + px[480 + idx] + px[960 + idx] + px[1440 + idx] + hbs[idx];
            } else if (tid < 448) {
                int idx = 414 + (tid - 384);
                sm[base + O_AV + (tid - 384)] =
                    px[idx] + px[480 + idx] + px[960 + idx] + px[1440 + idx] + hbs[idx];
            } else if (tid < 448 + NHEADS) {
                int h = tid - 448;
                int bidx = (h < 4 ? h * 70 : 280);
                float sv[6];
#pragma unroll
                for (int j = 0; j < 6; ++j) {
                    int idx = bidx + 64 + j;
                    sv[j] = px[idx] + px[480 + idx] + px[960 + idx] + px[1440 + idx] + hbs[idx];
                }
                float* hp = sm + base + O_HP;
                hp[h * 8 + 0] = __expf(sv[0]);
                hp[h * 8 + 1] = sigmoidf_(sv[1]);
                float s0 = sv[2], s1 = sv[3], s2 = sv[4];
                float mx = fmaxf(s0, fmaxf(s1, s2));
                float e0 = __expf(s0 - mx), e1 = __expf(s1 - mx), e2 = __expf(s2 - mx);
                float inv = 1.f / (e0 + e1 + e2);
                hp[h * 8 + 3] = e0 * inv; hp[h * 8 + 4] = e1 * inv; hp[h * 8 + 5] = e2 * inv;
                hp[h * 8 + 2] = softplusf_(sv[5]) + 1.f;
            }
        }
        __syncthreads();  // S3

        // ---- E x2 (sequential, full block) ----
#pragma unroll 1
        for (int bat = 0; bat < 2; ++bat) {
            const int base = bat * PB;
            const float* Mem = sm + base + O_MEM;
            const float4* KV4 = reinterpret_cast<const float4*>(sm + base + O_KV);
            const float* hp   = sm + base + O_HP;
            const float* kred = sm + base + O_KRED;
            const float* pinv = sm + base + O_PINV;
            const float4* RW4rd = reinterpret_cast<const float4*>(sm + base + RWRD);
            const float* wwrd = sm + base + WWRD;
            const int s  = tid >> 2;
            const int pq = tid & 3;
            float ex[NHEADS];
            {
                float d[NHEADS] = {0.f, 0.f, 0.f, 0.f, 0.f};
                float nn = 0.f;
                const float* mr = Mem + s * MEMP + pq * 16;
#pragma unroll
                for (int j = 0; j < 4; ++j) {
                    float m0 = mr[4 * j], m1 = mr[4 * j + 1], m2 = mr[4 * j + 2], m3 = mr[4 * j + 3];
                    nn = fmaf(m0, m0, nn); nn = fmaf(m1, m1, nn);
                    nn = fmaf(m2, m2, nn); nn = fmaf(m3, m3, nn);
#pragma unroll
                    for (int h = 0; h < NHEADS; ++h) {
                        float4 kq = KV4[h * 16 + pq * 4 + j];
                        d[h] = fmaf(m0, kq.x, d[h]); d[h] = fmaf(m1, kq.y, d[h]);
                        d[h] = fmaf(m2, kq.z, d[h]); d[h] = fmaf(m3, kq.w, d[h]);
                    }
                }
#pragma unroll
                for (int o = 1; o <= 2; o <<= 1) {
#pragma unroll
                    for (int h = 0; h < NHEADS; ++h) d[h] += __shfl_xor_sync(0xffffffffu, d[h], o);
                    nn += __shfl_xor_sync(0xffffffffu, nn, o);
                }
                float mn = sqrtf(nn);
#pragma unroll
                for (int h = 0; h < NHEADS; ++h) {
                    float kn = sqrtf(kred[2 * h] + kred[2 * h + 1]);
                    float z = hp[h * 8 + 0] * (d[h] / (kn * mn + 1e-8f));
                    ex[h] = __expf(z);
                }
            }
            if (pq == 0) {
                float* exg = sm + base + O_EXG;
#pragma unroll
                for (int h = 0; h < NHEADS; ++h) exg[h * 130 + s + 1] = ex[h];
            }
            if (tid == 0) {
                float4 wp4 = RW4rd[0];
                float wpv[5] = {wp4.x * pinv[0], wp4.y * pinv[1], wp4.z * pinv[2],
                                wp4.w * pinv[3], wwrd[0] * pinv[4]};
#pragma unroll
                for (int h = 0; h < NHEADS; ++h)
                    st_remote64(pb[left] + (base + O_HALO + 10 + h * 2) * 4, pack2(ex[h], wpv[h]));
            }
            if (tid == (SL - 1) * 4) {
                float4 wp4 = RW4rd[SL - 1];
                float wpv[5] = {wp4.x * pinv[0], wp4.y * pinv[1], wp4.z * pinv[2],
                                wp4.w * pinv[3], wwrd[SL - 1] * pinv[4]};
#pragma unroll
                for (int h = 0; h < NHEADS; ++h)
                    st_remote64(pb[right] + (base + O_HALO + h * 2) * 4, pack2(ex[h], wpv[h]));
            }
            float tmp[NHEADS];
#pragma unroll
            for (int h = 0; h < NHEADS; ++h) tmp[h] = (pq == 0) ? ex[h] : 0.f;
#pragma unroll
            for (int o = 16; o > 0; o >>= 1)
#pragma unroll
                for (int h = 0; h < NHEADS; ++h)
                    tmp[h] += __shfl_xor_sync(0xffffffffu, tmp[h], o);
            if (lane == 0)
#pragma unroll
                for (int h = 0; h < NHEADS; ++h) sm[base + O_REDB + wrp * 5 + h] = tmp[h];
        }
        __syncthreads();  // S4
        if (tid < 16) {
            const int bat = tid >> 3, h = tid & 7;
            if (h < 5) {
                const int base = bat * PB;
                const float* redb = sm + base + O_REDB;
                float acc = 0.f;
#pragma unroll
                for (int w = 0; w < 16; ++w) acc += redb[w * 5 + h];
                sm[base + O_STATS + r * 5 + h] = acc;
#pragma unroll
                for (int c = 0; c < CSZ; ++c)
                    if (c != (int)r)
                        st_remote(pb[c] + (base + O_STATS + (int)r * 5 + h) * 4, acc);
            }
        }
        CLUSTER_SYNC();  // CS3

        // ---- F: parallel halves (A: tid<128, B: 128..255) + x prefetch ----
        if (tid < 256) {
            const int bat = tid >> 7, s = tid & 127;
            const int base = bat * PB;
            const float* stats = sm + base + O_STATS;
            const float* hp    = sm + base + O_HP;
            const float* pinv  = sm + base + O_PINV;
            const float* exg   = sm + base + O_EXG;
            const float* halo  = sm + base + O_HALO;
            const float4* RW4rd = reinterpret_cast<const float4*>(sm + base + RWRD);
            const float* wwrd  = sm + base + WWRD;
            float invgs[NHEADS];
#pragma unroll
            for (int h = 0; h < NHEADS; ++h)
                invgs[h] = 1.f / (stats[h] + stats[5 + h] + stats[10 + h] + stats[15 + h]);
            float4 wc4 = RW4rd[s];
            float wpc[5] = {wc4.x * pinv[0], wc4.y * pinv[1], wc4.z * pinv[2],
                            wc4.w * pinv[3], wwrd[s] * pinv[4]};
            float wpm[5], wpp[5];
            if (s > 0) {
                float4 w4 = RW4rd[s - 1];
                wpm[0] = w4.x * pinv[0]; wpm[1] = w4.y * pinv[1];
                wpm[2] = w4.z * pinv[2]; wpm[3] = w4.w * pinv[3];
                wpm[4] = wwrd[s - 1] * pinv[4];
            } else {
#pragma unroll
                for (int h = 0; h < NHEADS; ++h) wpm[h] = halo[h * 2 + 1];
            }
            if (s < SL - 1) {
                float4 w4 = RW4rd[s + 1];
                wpp[0] = w4.x * pinv[0]; wpp[1] = w4.y * pinv[1];
                wpp[2] = w4.z * pinv[2]; wpp[3] = w4.w * pinv[3];
                wpp[4] = wwrd[s + 1] * pinv[4];
            } else {
#pragma unroll
                for (int h = 0; h < NHEADS; ++h) wpp[h] = halo[10 + h * 2 + 1];
            }
            float wt[NHEADS];
#pragma unroll
            for (int h = 0; h < NHEADS; ++h) {
                float g = hp[h * 8 + 1];
                float exm = exg[h * 130 + s];
                float exc = exg[h * 130 + s + 1];
                float exp_ = exg[h * 130 + s + 2];
                float wgm = g * (exm * invgs[h]) + (1.f - g) * wpm[h];
                float wgc = g * (exc * invgs[h]) + (1.f - g) * wpc[h];
                float wgp = g * (exp_ * invgs[h]) + (1.f - g) * wpp[h];
                float wsh = hp[h * 8 + 3] * wgp + hp[h * 8 + 4] * wgc + hp[h * 8 + 5] * wgm;
                wt[h] = __powf(fmaxf(wsh, 0.f), hp[h * 8 + 2]);
            }
            reinterpret_cast<float4*>(sm + base + RWWR)[s] =
                make_float4(wt[0], wt[1], wt[2], wt[3]);
            (sm + base + WWWR)[s] = wt[4];
#pragma unroll
            for (int o = 16; o > 0; o >>= 1)
#pragma unroll
                for (int h = 0; h < NHEADS; ++h)
                    wt[h] += __shfl_xor_sync(0xffffffffu, wt[h], o);
            if (lane == 0) {
                const int wloc = (tid >> 5) - bat * 4;
#pragma unroll
                for (int h = 0; h < NHEADS; ++h)
                    sm[base + O_REDB + wloc * 5 + h] = wt[h];
            }
        } else if (t + 1 < TT) {
            const int bat = (tid >= 384) ? 1 : 0;
            const int m = tid & 127;
            sm[bat * PB + O_CTRL + m] = x[((2 * bp + bat) * TT + t + 1) * DIN + m];
        }
        __syncthreads();  // S7
        if (tid < 16) {
            const int bat = tid >> 3, h = tid & 7;
            if (h < 5) {
                const int base = bat * PB;
                const float* redb = sm + base + O_REDB;
                float acc = redb[h] + redb[5 + h] + redb[10 + h] + redb[15 + h];
                sm[base + O_SSUM + r * 5 + h] = acc;
#pragma unroll
                for (int c = 0; c < CSZ; ++c)
                    if (c != (int)r)
                        st_remote(pb[c] + (base + O_SSUM + (int)r * 5 + h) * 4, acc);
            }
        }
        CLUSTER_SYNC();  // CS5

        // ---- GH: parallel halves (A: tid<256, B: 256..511) ----
        {
            const int bat = tid >> 8;
            const int q = tid & 255;
            const int m = q & 63;
            const int ng = q >> 6;            // 4 groups x 32 slots
            const int base = bat * PB;
            const float* ssum = sm + base + O_SSUM;
            float* Mem = sm + base + O_MEM;
            const float4* RW4wr = reinterpret_cast<const float4*>(sm + base + RWWR);
            const float* wwwr = sm + base + WWWR;
            const float invW = 1.f / (ssum[4] + ssum[9] + ssum[14] + ssum[19] + 1e-8f);
            const float ev = (sm + base + O_EV)[m] * invW;
            const float av = (sm + base + O_AV)[m] * invW;
            if (q < NHEADS)
                (sm + base + O_PINV)[q] =
                    1.f / (ssum[q] + ssum[5 + q] + ssum[10 + q] + ssum[15 + q] + 1e-8f);
            float a0 = 0.f, a1 = 0.f, a2 = 0.f, a3 = 0.f;
            const int n0 = ng * 32;
#pragma unroll
            for (int n = n0; n < n0 + 32; ++n) {
                float wv = wwwr[n];
                float* mp = Mem + n * MEMP + m;
                float mv = *mp;
                mv = mv * (1.f - wv * ev) + wv * av;
                *mp = mv;
                float4 rv = RW4wr[n];
                a0 = fmaf(mv, rv.x, a0); a1 = fmaf(mv, rv.y, a1);
                a2 = fmaf(mv, rv.z, a2); a3 = fmaf(mv, rv.w, a3);
            }
            float* bufX = sm + base + O_BUF;
            bufX[ng * 256 + 0 * 64 + m] = a0;
            bufX[ng * 256 + 1 * 64 + m] = a1;
            bufX[ng * 256 + 2 * 64 + m] = a2;
            bufX[ng * 256 + 3 * 64 + m] = a3;
        }
        __syncthreads();  // S10
        if (tid < 256) {
            const int bat = tid >> 7, c = tid & 127;
            const int base = bat * PB;
            const float* bufX = sm + base + O_BUF;
            float v0 = 0.f, v1 = 0.f;
#pragma unroll
            for (int ng = 0; ng < 4; ++ng) {
                v0 += bufX[ng * 256 + 2 * c];
                v1 += bufX[ng * 256 + 2 * c + 1];
            }
            float* rp = sm + base + O_PX;
            rp[r * 256 + 2 * c]     = v0;
            rp[r * 256 + 2 * c + 1] = v1;
            unsigned long long pk = pack2(v0, v1);
#pragma unroll
            for (int cc = 0; cc < CSZ; ++cc)
                if (cc != (int)r)
                    st_remote64(pb[cc] + (base + O_PX + (int)r * 256 + 2 * c) * 4, pk);
        }
        CLUSTER_SYNC();  // CS6
        {
            const int bat = tid >> 8;
            const int c = tid & 255;
            const int base = bat * PB;
            const float* rp = sm + base + O_PX;
            const float* pinv = sm + base + O_PINV;
            sm[base + O_CTRL + 128 + c] =
                (rp[c] + rp[256 + c] + rp[512 + c] + rp[768 + c]) * pinv[c >> 6];
        }
        __syncthreads();  // S11
    }
}

extern "C" void kernel_launch(void* const* d_in, const int* in_sizes, int n_in,
                              void* d_out, int out_size) {
    const float* x  = (const float*)d_in[0];
    const float* Wc = (const float*)d_in[1];
    const float* bc = (const float*)d_in[2];
    const float* hk = (const float*)d_in[3];
    const float* hb = (const float*)d_in[4];
    float* out = (float*)d_out;

    const size_t smem = SMEM_FLOATS * sizeof(float);
    cudaFuncSetAttribute(ntm_kernel, cudaFuncAttributeMaxDynamicSharedMemorySize, (int)smem);
    ntm_kernel<<<(BATCH / 2) * CSZ, NT, smem>>>(x, Wc, bc, hk, hb, out);
}

// round 9
// speedup vs baseline: 1.4481x; 1.4481x over previous
#include <cuda_runtime.h>
#include <cstdint>
#include <math.h>

#define BATCH   32
#define TT      32
#define DIN     128
#define CSZ     4
#define SL      128
#define CTRLD   256
#define NHEADS  5
#define NT      512
#define MEMP    65

// ---- SMEM layout (float offsets) ----
#define OFF_MEM    0        // 8320
#define OFF_PX     8320     // 1920 : instr partials [cta][480]; rpart reuse
#define OFF_EXG    10240    // 650
#define OFF_HALO   10890    // 20
#define OFF_STATS  10910    // 20
#define OFF_SSUM   10930    // 20
#define OFF_REDB   10950    // 80
#define OFF_KRED   11030    // 10
#define OFF_HP     11040    // 40
#define OFF_PINV   11080    // 8
#define OFF_RWA    11088    // 512
#define OFF_RWB    11600    // 512
#define OFF_WWA    12112    // 128
#define OFF_WWB    12240    // 128
#define OFF_RVEC   12368    // 256
#define OFF_H64    12624    // 64
#define OFF_KV     12688    // 320
#define OFF_EV     13008    // 64
#define OFF_AV     13072    // 64
#define OFF_HBS    13136    // 480
#define OFF_BUF    13616    // 2048
#define OFF_XP     15664    // 2048 : XP[t][64] = x_t @ Wc_x + bc
#define OFF_SWC    17712    // 8192 : mm1 r-rows 0..127 cache, [wrp][k] float4
#define OFF_SHK    25904    // 30720 : mm2 full cache, k-major stride 480
#define SMEM_FLOATS 56624   // 226496 bytes

__device__ __forceinline__ float sigmoidf_(float v) { return 1.f / (1.f + __expf(-v)); }
__device__ __forceinline__ float softplusf_(float v) { return v > 20.f ? v : log1pf(__expf(v)); }

__device__ __forceinline__ uint32_t smem_u32(const void* p) {
    uint32_t a;
    asm("{ .reg .u64 t; cvta.to.shared.u64 t, %1; cvt.u32.u64 %0, t; }" : "=r"(a) : "l"(p));
    return a;
}
__device__ __forceinline__ uint32_t mapa_u32(uint32_t a, uint32_t rank) {
    uint32_t r;
    asm("mapa.shared::cluster.u32 %0, %1, %2;" : "=r"(r) : "r"(a), "r"(rank));
    return r;
}
__device__ __forceinline__ void st_remote(uint32_t a, float v) {
    asm volatile("st.shared::cluster.f32 [%0], %1;" :: "r"(a), "f"(v) : "memory");
}
__device__ __forceinline__ void st_remote64(uint32_t a, unsigned long long v) {
    asm volatile("st.shared::cluster.u64 [%0], %1;" :: "r"(a), "l"(v) : "memory");
}
__device__ __forceinline__ uint32_t ctarank() {
    uint32_t r; asm("mov.u32 %0, %%cluster_ctarank;" : "=r"(r)); return r;
}
#define CLUSTER_ARRIVE() asm volatile("barrier.cluster.arrive.aligned;" ::: "memory")
#define CLUSTER_WAIT()   asm volatile("barrier.cluster.wait.aligned;" ::: "memory")
#define CLUSTER_SYNC() do { CLUSTER_ARRIVE(); CLUSTER_WAIT(); } while (0)

__device__ __forceinline__ unsigned long long pack2(float a, float b) {
    return (unsigned long long)__float_as_uint(a) |
           ((unsigned long long)__float_as_uint(b) << 32);
}

__global__ __launch_bounds__(NT, 1) __cluster_dims__(CSZ, 1, 1)
void ntm_kernel(const float* __restrict__ x, const float* __restrict__ Wc,
                const float* __restrict__ bc, const float* __restrict__ hk,
                const float* __restrict__ hb, float* __restrict__ out)
{
    extern __shared__ float sm[];
    float* Mem   = sm + OFF_MEM;
    float* px    = sm + OFF_PX;
    float* rpart = sm + OFF_PX;
    float* exg   = sm + OFF_EXG;
    float* halo  = sm + OFF_HALO;
    float* stats = sm + OFF_STATS;
    float* ssum  = sm + OFF_SSUM;
    float* redb  = sm + OFF_REDB;
    float* kred  = sm + OFF_KRED;
    float* hp    = sm + OFF_HP;
    float* pinv  = sm + OFF_PINV;
    float* rvec  = sm + OFF_RVEC;
    float* h64   = sm + OFF_H64;
    float* kvec  = sm + OFF_KV;
    float4* KV4  = reinterpret_cast<float4*>(kvec);
    float* evec  = sm + OFF_EV;
    float* avec  = sm + OFF_AV;
    float* hbs   = sm + OFF_HBS;
    float* buf   = sm + OFF_BUF;
    float* XP    = sm + OFF_XP;
    float4* XP4  = reinterpret_cast<float4*>(XP);
    float4* SWC4 = reinterpret_cast<float4*>(sm + OFF_SWC);
    float* SHK   = sm + OFF_SHK;

    const int tid  = threadIdx.x;
    const int wrp  = tid >> 5;
    const int lane = tid & 31;
    const int b    = blockIdx.x >> 2;
    const uint32_t r = ctarank();
    const uint32_t left  = (r + 3) & 3;
    const uint32_t right = (r + 1) & 3;

    const uint32_t sbase = smem_u32(sm);
    uint32_t pb[CSZ];
#pragma unroll
    for (int c = 0; c < CSZ; ++c) pb[c] = mapa_u32(sbase, c);

    // ---- init state ----
    for (int i = tid; i < SL * MEMP; i += NT) Mem[i] = 0.f;
    for (int i = tid; i < 512; i += NT) (sm + OFF_RWA)[i] = 0.f;
    if (tid < SL)  (sm + OFF_WWA)[tid] = 0.f;
    if (tid < 256) rvec[tid] = 0.f;
    if (tid < 8)   pinv[tid] = 1.f;
    if (tid < 478) hbs[tid] = hb[tid];
    {
        const float4* W4 = reinterpret_cast<const float4*>(Wc);
        // mm1 r-rows 0..127 cache (global rows 128..255), [wrp][k]
        for (int i = tid; i < 16 * 128; i += NT) {
            int w = i >> 7, k = i & 127;
            SWC4[i] = W4[(128 + k) * 64 + (int)r * 16 + w];
        }
        // mm2 full 64-row cache
        for (int kk = 0; kk < 64; ++kk)
            if (tid < 478)
                SHK[kk * 480 + tid] = hk[((int)r * 64 + kk) * 478 + tid];
        // XP[t][c] = x_t @ Wc_x (+ bc), per CTA column chunk
        {
            const int tt = tid >> 4, cg = tid & 15;
            const float* xr = x + (b * TT + tt) * DIN;
            float4 acc = make_float4(0.f, 0.f, 0.f, 0.f);
            const float4* Wx = W4 + (int)r * 16 + cg;
#pragma unroll 8
            for (int k = 0; k < 128; ++k) {
                float xv = xr[k];
                float4 w = Wx[k * 64];
                acc.x = fmaf(xv, w.x, acc.x); acc.y = fmaf(xv, w.y, acc.y);
                acc.z = fmaf(xv, w.z, acc.z); acc.w = fmaf(xv, w.w, acc.w);
            }
            float4 b4 = reinterpret_cast<const float4*>(bc)[(int)r * 16 + cg];
            acc.x += b4.x; acc.y += b4.y; acc.z += b4.z; acc.w += b4.w;
            XP4[tt * 16 + cg] = acc;
        }
    }
    __syncthreads();
    CLUSTER_SYNC();

    for (int t = 0; t < TT; ++t) {
        const int par = t & 1;
        float* RWrd = sm + (par ? OFF_RWB : OFF_RWA);
        float* RWwr = sm + (par ? OFF_RWA : OFF_RWB);
        float4* RW4rd = reinterpret_cast<float4*>(RWrd);
        float4* RW4wr = reinterpret_cast<float4*>(RWwr);
        float* wwrd = sm + (par ? OFF_WWB : OFF_WWA);
        float* wwwr = sm + (par ? OFF_WWA : OFF_WWB);

        // ---- B: mm1 r-part only (XP holds x-part + bias) ----
        {
            float a0 = 0.f, a1 = 0.f, a2 = 0.f, a3 = 0.f;
            const float4* cw = SWC4 + wrp * 128;
#pragma unroll
            for (int i = 0; i < 4; ++i) {               // cached k=0..127
                int k = lane + 32 * i;
                float c = rvec[k];
                float4 w = cw[k];
                a0 = fmaf(c, w.x, a0); a1 = fmaf(c, w.y, a1);
                a2 = fmaf(c, w.z, a2); a3 = fmaf(c, w.w, a3);
            }
            const float4* W4s = reinterpret_cast<const float4*>(Wc)
                                + 256 * 64 + (int)r * 16 + wrp;
#pragma unroll
            for (int i = 0; i < 4; ++i) {               // streamed k=128..255
                int k = lane + 32 * i;
                float c = rvec[128 + k];
                float4 w = W4s[k * 64];
                a0 = fmaf(c, w.x, a0); a1 = fmaf(c, w.y, a1);
                a2 = fmaf(c, w.z, a2); a3 = fmaf(c, w.w, a3);
            }
#pragma unroll
            for (int o = 16; o > 0; o >>= 1) {
                a0 += __shfl_xor_sync(0xffffffffu, a0, o);
                a1 += __shfl_xor_sync(0xffffffffu, a1, o);
                a2 += __shfl_xor_sync(0xffffffffu, a2, o);
                a3 += __shfl_xor_sync(0xffffffffu, a3, o);
            }
            if (lane < 4) {
                float av = (lane == 0) ? a0 : (lane == 1) ? a1 : (lane == 2) ? a2 : a3;
                float hv = tanhf(av + XP[t * 64 + 4 * wrp + lane]);
                h64[4 * wrp + lane] = hv;
                if (t == TT - 1) out[b * CTRLD + (int)r * 64 + 4 * wrp + lane] = hv;
            }
        }
        __syncthreads();  // S1

        // ---- C: mm2 single pass, full SMEM ----
        if (wrp < 15) {
            float v = 0.f;
#pragma unroll 16
            for (int k = 0; k < 64; ++k)
                v = fmaf(h64[k], SHK[k * 480 + tid], v);
            if (tid < 478) px[r * 480 + tid] = v;
            float vo = __shfl_down_sync(0xffffffffu, v, 1);
            if (!(tid & 1) && tid < 477) {
                unsigned long long pk = pack2(v, vo);
#pragma unroll
                for (int c = 0; c < CSZ; ++c)
                    if (c != (int)r)
                        st_remote64(pb[c] + (OFF_PX + (int)r * 480 + tid) * 4, pk);
            }
        }
        CLUSTER_ARRIVE();  // CS2 arrive

        // ---- CS2 gap: Mem norms (Mem stable since GH) ----
        const int s  = tid >> 2;
        const int pq = tid & 3;
        float mn_reg;
        {
            float nn = 0.f;
            const float* mr = Mem + s * MEMP + pq * 16;
#pragma unroll
            for (int j = 0; j < 16; ++j) nn = fmaf(mr[j], mr[j], nn);
            nn += __shfl_xor_sync(0xffffffffu, nn, 1);
            nn += __shfl_xor_sync(0xffffffffu, nn, 2);
            mn_reg = sqrtf(nn);
        }
        CLUSTER_WAIT();    // CS2 wait

        // ---- D: parse (fold partials) ----
        if (tid < 320) {
            int h = tid >> 6, m = tid & 63;
            int idx = (h < 4 ? h * 70 : 280) + m;
            float v = px[idx] + px[480 + idx] + px[960 + idx] + px[1440 + idx] + hbs[idx];
            kvec[tid] = v;
            float sq = v * v;
#pragma unroll
            for (int o = 16; o > 0; o >>= 1) sq += __shfl_xor_sync(0xffffffffu, sq, o);
            if (lane == 0) kred[wrp] = sq;
        } else if (tid < 384) {
            int idx = 350 + (tid - 320);
            evec[tid - 320] = px[idx] + px[480 + idx] + px[960 + idx] + px[1440 + idx] + hbs[idx];
        } else if (tid < 448) {
            int idx = 414 + (tid - 384);
            avec[tid - 384] = px[idx] + px[480 + idx] + px[960 + idx] + px[1440 + idx] + hbs[idx];
        } else if (tid < 448 + NHEADS) {
            int h = tid - 448;
            int bidx = (h < 4 ? h * 70 : 280);
            float sv[6];
#pragma unroll
            for (int j = 0; j < 6; ++j) {
                int idx = bidx + 64 + j;
                sv[j] = px[idx] + px[480 + idx] + px[960 + idx] + px[1440 + idx] + hbs[idx];
            }
            hp[h * 8 + 0] = __expf(sv[0]);
            hp[h * 8 + 1] = sigmoidf_(sv[1]);
            float s0 = sv[2], s1 = sv[3], s2 = sv[4];
            float mx = fmaxf(s0, fmaxf(s1, s2));
            float e0 = __expf(s0 - mx), e1 = __expf(s1 - mx), e2 = __expf(s2 - mx);
            float inv = 1.f / (e0 + e1 + e2);
            hp[h * 8 + 3] = e0 * inv; hp[h * 8 + 4] = e1 * inv; hp[h * 8 + 5] = e2 * inv;
            hp[h * 8 + 2] = softplusf_(sv[5]) + 1.f;
        }
        __syncthreads();  // S3

        // ---- E: sim + exp (nn precomputed) ----
        float ex[NHEADS];
        {
            float d[NHEADS] = {0.f, 0.f, 0.f, 0.f, 0.f};
            const float* mr = Mem + s * MEMP + pq * 16;
#pragma unroll
            for (int j = 0; j < 4; ++j) {
                float m0 = mr[4 * j], m1 = mr[4 * j + 1], m2 = mr[4 * j + 2], m3 = mr[4 * j + 3];
#pragma unroll
                for (int h = 0; h < NHEADS; ++h) {
                    float4 kq = KV4[h * 16 + pq * 4 + j];
                    d[h] = fmaf(m0, kq.x, d[h]); d[h] = fmaf(m1, kq.y, d[h]);
                    d[h] = fmaf(m2, kq.z, d[h]); d[h] = fmaf(m3, kq.w, d[h]);
                }
            }
#pragma unroll
            for (int o = 1; o <= 2; o <<= 1)
#pragma unroll
                for (int h = 0; h < NHEADS; ++h) d[h] += __shfl_xor_sync(0xffffffffu, d[h], o);
#pragma unroll
            for (int h = 0; h < NHEADS; ++h) {
                float kn = sqrtf(kred[2 * h] + kred[2 * h + 1]);
                float z = hp[h * 8 + 0] * (d[h] / (kn * mn_reg + 1e-8f));
                ex[h] = __expf(z);
            }
        }
        if (pq == 0) {
#pragma unroll
            for (int h = 0; h < NHEADS; ++h) exg[h * 130 + s + 1] = ex[h];
        }
        if (tid == 0) {
            float4 wp4 = RW4rd[0];
            float wpv[5] = {wp4.x * pinv[0], wp4.y * pinv[1], wp4.z * pinv[2],
                            wp4.w * pinv[3], wwrd[0] * pinv[4]};
#pragma unroll
            for (int h = 0; h < NHEADS; ++h)
                st_remote64(pb[left] + (OFF_HALO + 10 + h * 2) * 4, pack2(ex[h], wpv[h]));
        }
        if (tid == (SL - 1) * 4) {
            float4 wp4 = RW4rd[SL - 1];
            float wpv[5] = {wp4.x * pinv[0], wp4.y * pinv[1], wp4.z * pinv[2],
                            wp4.w * pinv[3], wwrd[SL - 1] * pinv[4]};
#pragma unroll
            for (int h = 0; h < NHEADS; ++h)
                st_remote64(pb[right] + (OFF_HALO + h * 2) * 4, pack2(ex[h], wpv[h]));
        }
        {
            float tmp[NHEADS];
#pragma unroll
            for (int h = 0; h < NHEADS; ++h) tmp[h] = (pq == 0) ? ex[h] : 0.f;
#pragma unroll
            for (int o = 16; o > 0; o >>= 1)
#pragma unroll
                for (int h = 0; h < NHEADS; ++h)
                    tmp[h] += __shfl_xor_sync(0xffffffffu, tmp[h], o);
            if (lane == 0)
#pragma unroll
                for (int h = 0; h < NHEADS; ++h) redb[wrp * 5 + h] = tmp[h];
        }
        __syncthreads();  // S4
        if (tid < NHEADS) {
            float acc = 0.f;
#pragma unroll
            for (int w = 0; w < 16; ++w) acc += redb[w * 5 + tid];
            stats[r * 5 + tid] = acc;
#pragma unroll
            for (int c = 0; c < CSZ; ++c)
                if (c != (int)r) st_remote(pb[c] + (OFF_STATS + (int)r * 5 + tid) * 4, acc);
        }
        CLUSTER_ARRIVE();  // CS3 arrive

        // ---- CS3 gap: preload F's local wp values (raw) ----
        float wpcR[5], wpmR[5], wppR[5];
        if (tid < SL) {
            float4 wc4 = RW4rd[tid];
            wpcR[0] = wc4.x; wpcR[1] = wc4.y; wpcR[2] = wc4.z; wpcR[3] = wc4.w;
            wpcR[4] = wwrd[tid];
            int im = (tid > 0) ? tid - 1 : 0;
            int ip = (tid < SL - 1) ? tid + 1 : SL - 1;
            float4 w4m = RW4rd[im];
            wpmR[0] = w4m.x; wpmR[1] = w4m.y; wpmR[2] = w4m.z; wpmR[3] = w4m.w;
            wpmR[4] = wwrd[im];
            float4 w4p = RW4rd[ip];
            wppR[0] = w4p.x; wppR[1] = w4p.y; wppR[2] = w4p.z; wppR[3] = w4p.w;
            wppR[4] = wwrd[ip];
        }
        CLUSTER_WAIT();    // CS3 wait

        // ---- F fused: wg + shift + sharpen ----
        if (tid < SL) {
            float wt[NHEADS];
            float invgs[NHEADS];
#pragma unroll
            for (int h = 0; h < NHEADS; ++h)
                invgs[h] = 1.f / (stats[h] + stats[5 + h] + stats[10 + h] + stats[15 + h]);
#pragma unroll
            for (int h = 0; h < NHEADS; ++h) {
                float pv = pinv[h];
                float wpm = (tid > 0)      ? wpmR[h] * pv : halo[h * 2 + 1];
                float wpc = wpcR[h] * pv;
                float wpp = (tid < SL - 1) ? wppR[h] * pv : halo[10 + h * 2 + 1];
                float g = hp[h * 8 + 1];
                float exm = exg[h * 130 + tid];
                float exc = exg[h * 130 + tid + 1];
                float exp_ = exg[h * 130 + tid + 2];
                float wgm = g * (exm * invgs[h]) + (1.f - g) * wpm;
                float wgc = g * (exc * invgs[h]) + (1.f - g) * wpc;
                float wgp = g * (exp_ * invgs[h]) + (1.f - g) * wpp;
                float wsh = hp[h * 8 + 3] * wgp + hp[h * 8 + 4] * wgc + hp[h * 8 + 5] * wgm;
                wt[h] = __powf(fmaxf(wsh, 0.f), hp[h * 8 + 2]);
            }
            RW4wr[tid] = make_float4(wt[0], wt[1], wt[2], wt[3]);
            wwwr[tid] = wt[4];
#pragma unroll
            for (int o = 16; o > 0; o >>= 1)
#pragma unroll
                for (int h = 0; h < NHEADS; ++h)
                    wt[h] += __shfl_xor_sync(0xffffffffu, wt[h], o);
            if (lane == 0)
#pragma unroll
                for (int h = 0; h < NHEADS; ++h) redb[wrp * 5 + h] = wt[h];
        }
        __syncthreads();  // S7
        if (tid < NHEADS) {
            float acc = redb[tid] + redb[5 + tid] + redb[10 + tid] + redb[15 + tid];
            ssum[r * 5 + tid] = acc;
#pragma unroll
            for (int c = 0; c < CSZ; ++c)
                if (c != (int)r) st_remote(pb[c] + (OFF_SSUM + (int)r * 5 + tid) * 4, acc);
        }
        CLUSTER_ARRIVE();  // CS5 arrive

        // ---- CS5 gap: GH pre-work (invW-independent by linearity) ----
        const int m  = tid & 63;
        const int ng = tid >> 6;
        const int n0 = ng * 16;
        const float evr = evec[m], avr = avec[m];
        float a0 = 0.f, a1 = 0.f, a2 = 0.f, a3 = 0.f;
        float u0 = 0.f, u1 = 0.f, u2 = 0.f, u3 = 0.f;
#pragma unroll
        for (int n = n0; n < n0 + 16; ++n) {
            float wv = wwwr[n];
            float mv = Mem[n * MEMP + m];
            float un = wv * (avr - mv * evr);
            float4 rv = RW4wr[n];
            a0 = fmaf(mv, rv.x, a0); a1 = fmaf(mv, rv.y, a1);
            a2 = fmaf(mv, rv.z, a2); a3 = fmaf(mv, rv.w, a3);
            u0 = fmaf(un, rv.x, u0); u1 = fmaf(un, rv.y, u1);
            u2 = fmaf(un, rv.z, u2); u3 = fmaf(un, rv.w, u3);
        }
        CLUSTER_WAIT();    // CS5 wait

        // ---- GH finish: fold invW, update Mem, emit read partials ----
        {
            if (tid < NHEADS)
                pinv[tid] = 1.f / (ssum[tid] + ssum[5 + tid] + ssum[10 + tid] + ssum[15 + tid] + 1e-8f);
            const float invW = 1.f / (ssum[4] + ssum[9] + ssum[14] + ssum[19] + 1e-8f);
#pragma unroll
            for (int n = n0; n < n0 + 16; ++n) {
                float* mp = Mem + n * MEMP + m;
                float mv = *mp;
                float wv = wwwr[n];
                *mp = mv + invW * (wv * (avr - mv * evr));
            }
            buf[ng * 256 + 0 * 64 + m] = fmaf(invW, u0, a0);
            buf[ng * 256 + 1 * 64 + m] = fmaf(invW, u1, a1);
            buf[ng * 256 + 2 * 64 + m] = fmaf(invW, u2, a2);
            buf[ng * 256 + 3 * 64 + m] = fmaf(invW, u3, a3);
        }
        __syncthreads();  // S10
        if (tid < 128) {
            float v0 = 0.f, v1 = 0.f;
#pragma unroll
            for (int g2 = 0; g2 < 8; ++g2) {
                v0 += buf[g2 * 256 + 2 * tid];
                v1 += buf[g2 * 256 + 2 * tid + 1];
            }
            rpart[r * 256 + 2 * tid]     = v0;
            rpart[r * 256 + 2 * tid + 1] = v1;
            unsigned long long pk = pack2(v0, v1);
#pragma unroll
            for (int c = 0; c < CSZ; ++c)
                if (c != (int)r)
                    st_remote64(pb[c] + (OFF_PX + (int)r * 256 + 2 * tid) * 4, pk);
        }
        CLUSTER_SYNC();  // CS6
        if (tid < 256) {
            int h = tid >> 6;
            rvec[tid] = (rpart[tid] + rpart[256 + tid] + rpart[512 + tid] + rpart[768 + tid])
                        * pinv[h];
        }
        __syncthreads();  // S11
    }
}

extern "C" void kernel_launch(void* const* d_in, const int* in_sizes, int n_in,
                              void* d_out, int out_size) {
    const float* x  = (const float*)d_in[0];
    const float* Wc = (const float*)d_in[1];
    const float* bc = (const float*)d_in[2];
    const float* hk = (const float*)d_in[3];
    const float* hb = (const float*)d_in[4];
    float* out = (float*)d_out;

    const size_t smem = SMEM_FLOATS * sizeof(float);
    cudaFuncSetAttribute(ntm_kernel, cudaFuncAttributeMaxDynamicSharedMemorySize, (int)smem);
    ntm_kernel<<<BATCH * CSZ, NT, smem>>>(x, Wc, bc, hk, hb, out);
}